// round 5
// baseline (speedup 1.0000x reference)
#include <cuda_runtime.h>
#include <math.h>
#include <stdint.h>

#define BDIM 4096
#define RDIM 64
#define DDIM 512
#define BB   32
#define NBLOCK (BDIM / BB)     // 128
#define NTHREADS 512
#define NWARPS 16
#define ROWF 516               // padded row stride (floats): 516 mod 32 == 4
#define W_TILE_F (BB * ROWF)   // 16512
#define E_TILE_F (RDIM * ROWF) // 33024
#define DYN_SMEM ((W_TILE_F + E_TILE_F) * 4)   // 198144 B

__device__ float g_partial[NBLOCK];
__device__ int   g_count = 0;

__device__ __forceinline__ uint32_t smem_u32(const void* p) {
    return (uint32_t)__cvta_generic_to_shared(p);
}
__device__ __forceinline__ void bulk_cp(uint32_t dst, const void* src,
                                        uint32_t bytes, uint32_t mbar) {
    asm volatile(
        "cp.async.bulk.shared::cta.global.mbarrier::complete_tx::bytes [%0], [%1], %2, [%3];"
        :: "r"(dst), "l"(src), "r"(bytes), "r"(mbar) : "memory");
}
__device__ __forceinline__ void mbar_init(uint32_t mbar, uint32_t cnt) {
    asm volatile("mbarrier.init.shared.b64 [%0], %1;" :: "r"(mbar), "r"(cnt) : "memory");
}
__device__ __forceinline__ void mbar_expect_tx(uint32_t mbar, uint32_t bytes) {
    asm volatile("mbarrier.arrive.expect_tx.shared.b64 _, [%0], %1;"
                 :: "r"(mbar), "r"(bytes) : "memory");
}
__device__ __forceinline__ void mbar_wait(uint32_t mbar, uint32_t parity) {
    asm volatile(
        "{\n\t.reg .pred P;\n\t"
        "WL_%=:\n\t"
        "mbarrier.try_wait.parity.acquire.cta.shared::cta.b64 P, [%0], %1, 0x989680;\n\t"
        "@P bra.uni WD_%=;\n\t"
        "bra.uni WL_%=;\n\t"
        "WD_%=:\n\t}"
        :: "r"(mbar), "r"(parity) : "memory");
}
// packed f32x2 fma: two independent fp32 FMAs per instruction
__device__ __forceinline__ double ffma2(double a, double b, double c) {
    double d;
    asm("fma.rn.f32x2 %0, %1, %2, %3;" : "=d"(d) : "d"(a), "d"(b), "d"(c));
    return d;
}

__global__ __launch_bounds__(NTHREADS, 1)
void fused_kernel(const float* __restrict__ w,
                  const float* __restrict__ e,
                  const float* __restrict__ label,
                  float* __restrict__ out, int out_size)
{
    extern __shared__ __align__(16) float dyn[];
    float* w_s = dyn;                 // [BB][ROWF]
    float* e_s = dyn + W_TILE_F;      // [RDIM][ROWF]

    __shared__ __align__(8) uint64_t mbar_storage;
    __shared__ float ne_red[RDIM][9];
    __shared__ float ne_s[RDIM];
    __shared__ float nw_red[BB][17];
    __shared__ float s_s[RDIM][33];
    __shared__ float red_m1[NWARPS][32], red_m2[NWARPS][32], red_lm[NWARPS][32];
    __shared__ int   red_i1[NWARPS][32], red_i2[NWARPS][32], red_li[NWARPS][32];
    __shared__ int   idx1_s[32];
    __shared__ float fs[NBLOCK];
    __shared__ int   is_last;

    const int tid  = threadIdx.x;
    const int lane = tid & 31;
    const int wid  = tid >> 5;
    const int b0   = blockIdx.x * BB;
    const uint32_t mbar = smem_u32(&mbar_storage);

    // ---- stage entire w tile (32 rows) + entire e (64 rows) via bulk async copy
    if (tid == 0) mbar_init(mbar, 1);
    __syncthreads();
    if (tid == 0) mbar_expect_tx(mbar, (BB + RDIM) * DDIM * 4);
    __syncthreads();
    if (tid < BB) {
        bulk_cp(smem_u32(w_s + tid * ROWF),
                w + (size_t)(b0 + tid) * DDIM, DDIM * 4, mbar);
    } else if (tid < BB + RDIM) {
        int r = tid - BB;
        bulk_cp(smem_u32(e_s + r * ROWF),
                e + (size_t)r * DDIM, DDIM * 4, mbar);
    }
    mbar_wait(mbar, 0);

    // ---- main loop first (norms are only needed by the epilogue) ----
    // warp -> 4 relations, lane: bg = lane>>2 (b = bg+8k), rg = lane&3
    const int bg = lane >> 2;
    const int rg = lane & 3;
    const int rr = wid * 4 + rg;            // this thread's relation
    const float* wp0 = w_s + bg * ROWF;
    const float* ep0 = e_s + rr * ROWF;

    double acc[4];
#pragma unroll
    for (int k = 0; k < 4; k++) acc[k] = 0.0;

#pragma unroll 4
    for (int g = 0; g < DDIM / 4; g++) {
        const int d = g * 4;
        float4 ef = *reinterpret_cast<const float4*>(ep0 + d);
        double2 ed = *reinterpret_cast<double2*>(&ef);
#pragma unroll
        for (int k = 0; k < 4; k++) {
            float4 wf = *reinterpret_cast<const float4*>(wp0 + k * 8 * ROWF + d);
            double2 wd = *reinterpret_cast<double2*>(&wf);
            acc[k] = ffma2(wd.x, ed.x, acc[k]);
            acc[k] = ffma2(wd.y, ed.y, acc[k]);
        }
    }

    // ---- ||e_r||^2 partials: r = tid>>3 (0..63), slice = tid&7 (16 float4) ----
    {
        const int r = tid >> 3, sl = tid & 7;
        const float4* p = reinterpret_cast<const float4*>(e_s + r * ROWF + sl * 64);
        float a = 0.f;
#pragma unroll 4
        for (int k = 0; k < 16; k++) {
            float4 v = p[k];
            a = fmaf(v.x, v.x, a); a = fmaf(v.y, v.y, a);
            a = fmaf(v.z, v.z, a); a = fmaf(v.w, v.w, a);
        }
        ne_red[r][sl] = a;
    }
    // ---- ||w_b||^2 partials: bl = tid>>4 (0..31), slice = tid&15 (8 float4) ----
    {
        const int bl = tid >> 4, sl = tid & 15;
        const float4* p = reinterpret_cast<const float4*>(w_s + bl * ROWF + sl * 32);
        float a = 0.f;
#pragma unroll
        for (int k = 0; k < 8; k++) {
            float4 v = p[k];
            a = fmaf(v.x, v.x, a); a = fmaf(v.y, v.y, a);
            a = fmaf(v.z, v.z, a); a = fmaf(v.w, v.w, a);
        }
        nw_red[bl][sl] = a;
    }
    __syncthreads();
    if (tid < RDIM) {
        float a = 0.f;
#pragma unroll
        for (int k = 0; k < 8; k++) a += ne_red[tid][k];
        ne_s[tid] = a;
    }
    __syncthreads();

    // ---- s = ||e||^2 - 2 w.e into s_s[r][b] ----
    {
        const float ne_r = ne_s[rr];
#pragma unroll
        for (int k = 0; k < 4; k++) {
            float2 h = *reinterpret_cast<float2*>(&acc[k]);
            float dot = h.x + h.y;
            s_s[rr][bg + 8 * k] = fmaf(-2.f, dot, ne_r);
        }
    }
    __syncthreads();

    // ---- per-warp top-2 over its 4 relations (lane = b, first-index ties) ----
    const int r0w = wid * 4;
    float m1 = -1e30f, m2 = -1e30f;
    int   i1 = r0w, i2 = r0w;
#pragma unroll
    for (int j = 0; j < 4; j++) {
        float sv = s_s[r0w + j][lane];
        if (sv > m1)      { m2 = m1; i2 = i1; m1 = sv; i1 = r0w + j; }
        else if (sv > m2) { m2 = sv; i2 = r0w + j; }
    }
    // ---- label local argmax over this warp's 4 relations ----
    {
        const float* lp = label + (size_t)(b0 + lane) * RDIM + r0w;
        float4 la = reinterpret_cast<const float4*>(lp)[0];
        float lv[4] = {la.x, la.y, la.z, la.w};
        float lm = lv[0]; int li = r0w;
#pragma unroll
        for (int j = 1; j < 4; j++)
            if (lv[j] > lm) { lm = lv[j]; li = r0w + j; }
        red_lm[wid][lane] = lm;
        red_li[wid][lane] = li;
    }
    red_m1[wid][lane] = m1;  red_i1[wid][lane] = i1;
    red_m2[wid][lane] = m2;  red_i2[wid][lane] = i2;
    __syncthreads();

    // ---- per-row merge across the 16 warps (warp 0, lane = row) ----
    if (wid == 0) {
        float v1 = red_m1[0][lane]; int ix1 = red_i1[0][lane];
        float v2 = red_m2[0][lane]; int ix2 = red_i2[0][lane];
        float LV = red_lm[0][lane]; int LI  = red_li[0][lane];
#pragma unroll
        for (int g = 1; g < NWARPS; g++) {
            float a1 = red_m1[g][lane]; int aj1 = red_i1[g][lane];
            float a2 = red_m2[g][lane]; int aj2 = red_i2[g][lane];
            if (a1 > v1) {
                if (a2 > v1) { v2 = a2; ix2 = aj2; }
                else         { v2 = v1; ix2 = ix1; }
                v1 = a1; ix1 = aj1;
            } else if (a1 > v2) {
                v2 = a1; ix2 = aj1;
            }
            float al = red_lm[g][lane];
            if (al > LV) { LV = al; LI = red_li[g][lane]; }
        }
        float nw = 0.f;
#pragma unroll
        for (int k = 0; k < 16; k++) nw += nw_red[lane][k];

        const int y = LI;
        float plus2  = fmaxf(nw + s_s[y][lane], 0.f);
        float minus2 = fmaxf(nw + ((ix1 == y) ? v2 : v1), 0.f);
        float loss_b = 1.f + sqrtf(plus2) - sqrtf(minus2);
        idx1_s[lane] = ix1;
        (void)ix2;
#pragma unroll
        for (int off = 16; off; off >>= 1)
            loss_b += __shfl_xor_sync(0xFFFFFFFFu, loss_b, off);
        if (lane == 0) g_partial[blockIdx.x] = loss_b;
    }
    __syncthreads();

    // ---- coalesced one-hot pred write: one float4 per thread ----
    {
        float4* op = reinterpret_cast<float4*>(out + (size_t)b0 * RDIM);
        int bl = tid >> 4;              // local b row
        int r  = (tid & 15) * 4;        // relation offset
        int p  = idx1_s[bl];
        float4 v;
        v.x = (r + 0 == p) ? 1.f : 0.f;
        v.y = (r + 1 == p) ? 1.f : 0.f;
        v.z = (r + 2 == p) ? 1.f : 0.f;
        v.w = (r + 3 == p) ? 1.f : 0.f;
        op[tid] = v;
    }

    // ---- fused finalize: last block reduces g_partial deterministically ----
    if (tid == 0) {
        __threadfence();
        int c = atomicAdd(&g_count, 1);
        is_last = (c == gridDim.x - 1) ? 1 : 0;
    }
    __syncthreads();
    if (is_last) {
        __threadfence();
        if (tid < NBLOCK) fs[tid] = g_partial[tid];
        __syncthreads();
#pragma unroll
        for (int off = NBLOCK / 2; off > 0; off >>= 1) {
            if (tid < off) fs[tid] += fs[tid + off];
            __syncthreads();
        }
        if (tid == 0) {
            out[out_size - 1] = fs[0] * (1.0f / (float)BDIM);
            g_count = 0;
        }
    }
}

extern "C" void kernel_launch(void* const* d_in, const int* in_sizes, int n_in,
                              void* d_out, int out_size)
{
    const float* w     = (const float*)d_in[0];   // [4096, 512]
    const float* e     = (const float*)d_in[1];   // [64, 512]
    const float* label = (const float*)d_in[2];   // [4096, 64]
    float* out = (float*)d_out;                   // pred [4096*64] ++ loss [1]

    cudaFuncSetAttribute(fused_kernel,
                         cudaFuncAttributeMaxDynamicSharedMemorySize, DYN_SMEM);
    fused_kernel<<<NBLOCK, NTHREADS, DYN_SMEM>>>(w, e, label, out, out_size);
}

// round 7
// speedup vs baseline: 1.5050x; 1.5050x over previous
#include <cuda_runtime.h>
#include <math.h>
#include <stdint.h>

#define BDIM 4096
#define RDIM 64
#define DDIM 512
#define BB   32                 // batch rows per CTA
#define NBLOCK (BDIM / BB)      // 128 CTAs
#define NTHREADS 256
#define ROWF 516                // padded row stride (floats)
#define W_TILE_F (BB * ROWF)
#define E_TILE_F (RDIM * ROWF)
#define DYN_SMEM ((W_TILE_F + E_TILE_F) * 4)   // 198144 B

__device__ float g_partial[NBLOCK];
__device__ int   g_count = 0;

__device__ __forceinline__ uint32_t smem_u32(const void* p) {
    return (uint32_t)__cvta_generic_to_shared(p);
}
__device__ __forceinline__ void bulk_cp(uint32_t dst, const void* src,
                                        uint32_t bytes, uint32_t mbar) {
    asm volatile(
        "cp.async.bulk.shared::cta.global.mbarrier::complete_tx::bytes [%0], [%1], %2, [%3];"
        :: "r"(dst), "l"(src), "r"(bytes), "r"(mbar) : "memory");
}
__device__ __forceinline__ void mbar_init(uint32_t mbar, uint32_t cnt) {
    asm volatile("mbarrier.init.shared.b64 [%0], %1;" :: "r"(mbar), "r"(cnt) : "memory");
}
__device__ __forceinline__ void mbar_expect_tx(uint32_t mbar, uint32_t bytes) {
    asm volatile("mbarrier.arrive.expect_tx.shared.b64 _, [%0], %1;"
                 :: "r"(mbar), "r"(bytes) : "memory");
}
__device__ __forceinline__ void mbar_wait(uint32_t mbar, uint32_t parity) {
    asm volatile(
        "{\n\t.reg .pred P;\n\t"
        "WL_%=:\n\t"
        "mbarrier.try_wait.parity.acquire.cta.shared::cta.b64 P, [%0], %1, 0x989680;\n\t"
        "@P bra.uni WD_%=;\n\t"
        "bra.uni WL_%=;\n\t"
        "WD_%=:\n\t}"
        :: "r"(mbar), "r"(parity) : "memory");
}
// split fp32 into tf32-exact hi + residual lo (both bit patterns for mma)
__device__ __forceinline__ void split_u(float x, uint32_t& hi, uint32_t& lo) {
    uint32_t xb = __float_as_uint(x);
    hi = xb & 0xFFFFE000u;
    lo = __float_as_uint(x - __uint_as_float(hi));
}
__device__ __forceinline__ void mma_tf32(float* c, const uint32_t* a,
                                         uint32_t b0, uint32_t b1) {
    asm volatile(
        "mma.sync.aligned.m16n8k8.row.col.f32.tf32.tf32.f32 "
        "{%0,%1,%2,%3}, {%4,%5,%6,%7}, {%8,%9}, {%0,%1,%2,%3};"
        : "+f"(c[0]), "+f"(c[1]), "+f"(c[2]), "+f"(c[3])
        : "r"(a[0]), "r"(a[1]), "r"(a[2]), "r"(a[3]), "r"(b0), "r"(b1));
}

__global__ __launch_bounds__(NTHREADS, 1)
void fused_kernel(const float* __restrict__ w,
                  const float* __restrict__ e,
                  const float* __restrict__ label,
                  float* __restrict__ out, int out_size)
{
    extern __shared__ __align__(16) float dyn[];
    float* w_s = dyn;                 // [BB][ROWF]
    float* e_s = dyn + W_TILE_F;      // [RDIM][ROWF]

    __shared__ __align__(8) uint64_t mbar_sto;
    __shared__ float s_s[BB][65];     // dot products [b][r]
    __shared__ float ne_red[RDIM][4];
    __shared__ float ne_s[RDIM];
    __shared__ float nw_red[BB][9];
    __shared__ int   idx1_s[BB];
    __shared__ float fs[NBLOCK];
    __shared__ int   is_last;

    const int tid  = threadIdx.x;
    const int lane = tid & 31;
    const int wid  = tid >> 5;
    const int b0   = blockIdx.x * BB;
    const uint32_t mbar = smem_u32(&mbar_sto);

    // ---- stage w tile (32 rows) + e (64 rows) via bulk async copy ----
    if (tid == 0) mbar_init(mbar, 1);
    __syncthreads();
    if (tid == 0) mbar_expect_tx(mbar, (BB + RDIM) * DDIM * 4);
    __syncthreads();
    if (tid < BB) {
        bulk_cp(smem_u32(w_s + tid * ROWF),
                w + (size_t)(b0 + tid) * DDIM, DDIM * 4, mbar);
    } else if (tid < BB + RDIM) {
        int r = tid - BB;
        bulk_cp(smem_u32(e_s + r * ROWF),
                e + (size_t)r * DDIM, DDIM * 4, mbar);
    }
    mbar_wait(mbar, 0);

    // ---- HMMA main loop: warp (mh,nq) computes 16 rows x 16 cols ----
    const int mh = wid >> 2;          // 0..1  (M half)
    const int nq = wid & 3;           // 0..3  (N quarter)
    const int gi = lane >> 2;         // groupID 0..7
    const int kk = lane & 3;          // threadID_in_group

    const int r_lo = 16 * mh + gi;
    const float* wlo = w_s + r_lo * ROWF + kk;
    const float* whi = wlo + 8 * ROWF;
    const float* eb0 = e_s + (16 * nq + gi) * ROWF + kk;
    const float* eb1 = eb0 + 8 * ROWF;

    float acc[2][2][4];               // [k-parity chain][n-tile][4]
#pragma unroll
    for (int p = 0; p < 2; p++)
#pragma unroll
        for (int t = 0; t < 2; t++)
#pragma unroll
            for (int i = 0; i < 4; i++) acc[p][t][i] = 0.f;

#pragma unroll 4
    for (int s = 0; s < DDIM / 8; s++) {
        const int k0 = s * 8;
        uint32_t ah[4], al[4];
        split_u(wlo[k0],     ah[0], al[0]);
        split_u(whi[k0],     ah[1], al[1]);
        split_u(wlo[k0 + 4], ah[2], al[2]);
        split_u(whi[k0 + 4], ah[3], al[3]);

        uint32_t b0h, b0l, b1h, b1l;
        float* c;
        // n-tile 0
        split_u(eb0[k0],     b0h, b0l);
        split_u(eb0[k0 + 4], b1h, b1l);
        c = acc[s & 1][0];
        mma_tf32(c, ah, b0h, b1h);
        mma_tf32(c, ah, b0l, b1l);
        mma_tf32(c, al, b0h, b1h);
        // n-tile 1
        split_u(eb1[k0],     b0h, b0l);
        split_u(eb1[k0 + 4], b1h, b1l);
        c = acc[s & 1][1];
        mma_tf32(c, ah, b0h, b1h);
        mma_tf32(c, ah, b0l, b1l);
        mma_tf32(c, al, b0h, b1h);
    }

    // ---- write dot products to s_s[b][r] ----
#pragma unroll
    for (int t = 0; t < 2; t++) {
        const int cb = 16 * nq + 8 * t + 2 * kk;
        s_s[r_lo][cb]         = acc[0][t][0] + acc[1][t][0];
        s_s[r_lo][cb + 1]     = acc[0][t][1] + acc[1][t][1];
        s_s[r_lo + 8][cb]     = acc[0][t][2] + acc[1][t][2];
        s_s[r_lo + 8][cb + 1] = acc[0][t][3] + acc[1][t][3];
    }

    // ---- norms from smem ----
    {   // ||e_r||^2: r = tid>>2 (0..63), slice = tid&3 (32 float4)
        const int r = tid >> 2, sl = tid & 3;
        const float4* p = reinterpret_cast<const float4*>(e_s + r * ROWF + sl * 128);
        float a = 0.f;
#pragma unroll 8
        for (int k = 0; k < 32; k++) {
            float4 v = p[k];
            a = fmaf(v.x, v.x, a); a = fmaf(v.y, v.y, a);
            a = fmaf(v.z, v.z, a); a = fmaf(v.w, v.w, a);
        }
        ne_red[r][sl] = a;
    }
    {   // ||w_b||^2: bl = tid>>3 (0..31), slice = tid&7 (16 float4)
        const int bl = tid >> 3, sl = tid & 7;
        const float4* p = reinterpret_cast<const float4*>(w_s + bl * ROWF + sl * 64);
        float a = 0.f;
#pragma unroll 4
        for (int k = 0; k < 16; k++) {
            float4 v = p[k];
            a = fmaf(v.x, v.x, a); a = fmaf(v.y, v.y, a);
            a = fmaf(v.z, v.z, a); a = fmaf(v.w, v.w, a);
        }
        nw_red[bl][sl] = a;
    }
    __syncthreads();
    if (tid < RDIM)
        ne_s[tid] = ne_red[tid][0] + ne_red[tid][1] + ne_red[tid][2] + ne_red[tid][3];
    __syncthreads();

    // ---- per-row epilogue: thread tid < 32 owns row b0+tid ----
    if (tid < BB) {
        const int r = tid;
        // label argmax (first-index tie-break)
        int y = 0;
        {
            const float4* lp = reinterpret_cast<const float4*>(
                label + (size_t)(b0 + r) * RDIM);
            float lm = -1e30f;
#pragma unroll
            for (int g = 0; g < 16; g++) {
                float4 v = lp[g];
                if (v.x > lm) { lm = v.x; y = g * 4; }
                if (v.y > lm) { lm = v.y; y = g * 4 + 1; }
                if (v.z > lm) { lm = v.z; y = g * 4 + 2; }
                if (v.w > lm) { lm = v.w; y = g * 4 + 3; }
            }
        }
        float m1 = -1e30f, m2 = -1e30f, s_y = 0.f;
        int i1 = 0;
#pragma unroll
        for (int c = 0; c < RDIM; c++) {
            float sv = fmaf(-2.f, s_s[r][c], ne_s[c]);
            if (c == y) s_y = sv;
            if (sv > m1)      { m2 = m1; m1 = sv; i1 = c; }
            else if (sv > m2) { m2 = sv; }
        }
        float nw = 0.f;
#pragma unroll
        for (int k = 0; k < 8; k++) nw += nw_red[r][k];

        float plus2  = fmaxf(nw + s_y, 0.f);
        float minus2 = fmaxf(nw + ((i1 == y) ? m2 : m1), 0.f);
        float loss_b = 1.f + sqrtf(plus2) - sqrtf(minus2);
        idx1_s[r] = i1;
#pragma unroll
        for (int off = 16; off; off >>= 1)
            loss_b += __shfl_xor_sync(0xFFFFFFFFu, loss_b, off);
        if (lane == 0) g_partial[blockIdx.x] = loss_b;
    }
    __syncthreads();

    // ---- coalesced one-hot pred write (2 float4 per thread) ----
    {
        float4* op = reinterpret_cast<float4*>(out + (size_t)b0 * RDIM);
#pragma unroll
        for (int k = 0; k < 2; k++) {
            int i  = tid * 8 + k * 4;
            int bl = i >> 6;
            int r  = i & 63;
            int p  = idx1_s[bl];
            float4 v;
            v.x = (r + 0 == p) ? 1.f : 0.f;
            v.y = (r + 1 == p) ? 1.f : 0.f;
            v.z = (r + 2 == p) ? 1.f : 0.f;
            v.w = (r + 3 == p) ? 1.f : 0.f;
            op[tid * 2 + k] = v;
        }
    }

    // ---- fused finalize: last block reduces g_partial deterministically ----
    if (tid == 0) {
        __threadfence();
        int c = atomicAdd(&g_count, 1);
        is_last = (c == gridDim.x - 1) ? 1 : 0;
    }
    __syncthreads();
    if (is_last) {
        __threadfence();
        if (tid < NBLOCK) fs[tid] = g_partial[tid];
        __syncthreads();
#pragma unroll
        for (int off = NBLOCK / 2; off > 0; off >>= 1) {
            if (tid < off) fs[tid] += fs[tid + off];
            __syncthreads();
        }
        if (tid == 0) {
            out[out_size - 1] = fs[0] * (1.0f / (float)BDIM);
            g_count = 0;
        }
    }
}

extern "C" void kernel_launch(void* const* d_in, const int* in_sizes, int n_in,
                              void* d_out, int out_size)
{
    const float* w     = (const float*)d_in[0];   // [4096, 512]
    const float* e     = (const float*)d_in[1];   // [64, 512]
    const float* label = (const float*)d_in[2];   // [4096, 64]
    float* out = (float*)d_out;                   // pred [4096*64] ++ loss [1]

    cudaFuncSetAttribute(fused_kernel,
                         cudaFuncAttributeMaxDynamicSharedMemorySize, DYN_SMEM);
    fused_kernel<<<NBLOCK, NTHREADS, DYN_SMEM>>>(w, e, label, out, out_size);
}